// round 12
// baseline (speedup 1.0000x reference)
#include <cuda_runtime.h>
#include <cuda_fp16.h>
#include <mma.h>

using namespace nvcuda;

// Problem dims: N=50000 nodes, E=800000 edges, in_dim=128, out_dim=64.
#define MAX_N   50176
#define MAX_E   803840
#define IN_DIM  128
#define OUT_DIM 64
#define NEG_SLOPE 0.2f

// Scratch (allocation-free: __device__ globals; zero-initialized at load).
__device__ __half2 g_hh2[MAX_N * (OUT_DIM / 2)];  // h [N,64] as half2
__device__ float g_hs[MAX_N];            // h @ a_src (fp32)
__device__ float g_hd[MAX_N];            // h @ a_dst (fp32)
__device__ int   g_deg[MAX_N];           // out-degree (zeroed by k_agg of prior call)
__device__ int   g_rowptr[MAX_N];        // CSR row pointers
__device__ int   g_cursor[MAX_N];        // scatter cursors
__device__ int   g_csrdst[MAX_E];        // dst ids grouped by src
// decoupled-lookback scan state (flags zeroed by k_scatter of prior call)
__device__ volatile int g_blockagg[256];
__device__ volatile int g_blockpre[256];
__device__ volatile int g_flag[256];

// ---------------------------------------------------------------------------
// K1: h = X @ W via wmma (fp16 inputs, fp32 accum). Block: 128 rows x 64 cols,
// 8 warps, each warp one 16-row stripe (4 wmma tiles along N). Fused: src
// histogram (grid-stride at start) and hs/hd projections (from fp32 accum).
// SMEM: Xs[128][128] half (32KB) + Wsh[128][64] half (16KB) = 48KB exactly;
// the fp32 result tile Cs (32KB) reuses Xs after the MMA phase.
// ---------------------------------------------------------------------------
__global__ __launch_bounds__(256) void k_gemm(const float* __restrict__ inp,
                                              const float* __restrict__ Wg,
                                              const float* __restrict__ ag,
                                              const int* __restrict__ edge,
                                              int N, int E) {
    __shared__ __align__(16) char smem_raw[49152];
    __half* Xs  = (__half*)smem_raw;              // [128][128], 32KB
    __half* Wsh = (__half*)(smem_raw + 32768);    // [128][64],  16KB
    float*  Cs  = (float*)smem_raw;               // [128][64] fp32, aliases Xs

    int tid = threadIdx.x;
    int row0 = blockIdx.x * 128;

    // fused histogram of edge src (g_deg pre-zeroed)
    {
        int gt = blockIdx.x * 256 + tid;
        int nth = gridDim.x * 256;
        for (int i = gt; i < E; i += nth) atomicAdd(&g_deg[edge[i]], 1);
    }

    // stage X block (fp32 -> fp16), zero-pad tail rows
    {
        const float4* X4 = (const float4*)inp;
        for (int i = tid; i < 128 * 32; i += 256) {     // 32 float4 per row
            int row = i >> 5;
            int c4  = i & 31;
            float4 f = (row0 + row < N)
                ? X4[(size_t)(row0 + row) * 32 + c4]
                : make_float4(0.f, 0.f, 0.f, 0.f);
            __half2 h0 = __floats2half2_rn(f.x, f.y);
            __half2 h1 = __floats2half2_rn(f.z, f.w);
            __half2* p = (__half2*)(Xs + row * 128 + c4 * 4);
            p[0] = h0; p[1] = h1;
        }
    }
    // stage W (fp32 -> fp16), [k][n] row-major
    {
        const float4* W4 = (const float4*)Wg;
        for (int i = tid; i < 2048; i += 256) {         // 8192 floats
            float4 f = W4[i];
            __half2* p = (__half2*)(Wsh + i * 4);
            p[0] = __floats2half2_rn(f.x, f.y);
            p[1] = __floats2half2_rn(f.z, f.w);
        }
    }
    __syncthreads();

    // MMA: warp w computes rows w*16..w*16+15, all 64 cols
    int w = tid >> 5;
    {
        wmma::fragment<wmma::accumulator, 16, 16, 16, float> c_frag[4];
#pragma unroll
        for (int n = 0; n < 4; n++) wmma::fill_fragment(c_frag[n], 0.0f);

#pragma unroll
        for (int k = 0; k < 8; k++) {
            wmma::fragment<wmma::matrix_a, 16, 16, 16, __half, wmma::row_major> a_frag;
            wmma::load_matrix_sync(a_frag, Xs + w * 16 * 128 + k * 16, 128);
#pragma unroll
            for (int n = 0; n < 4; n++) {
                wmma::fragment<wmma::matrix_b, 16, 16, 16, __half, wmma::row_major> b_frag;
                wmma::load_matrix_sync(b_frag, Wsh + k * 16 * 64 + n * 16, 64);
                wmma::mma_sync(c_frag[n], a_frag, b_frag, c_frag[n]);
            }
        }
        __syncthreads();   // Xs dead; Cs aliases it
#pragma unroll
        for (int n = 0; n < 4; n++)
            wmma::store_matrix_sync(Cs + w * 16 * 64 + n * 16, c_frag[n], 64,
                                    wmma::mem_row_major);
    }
    __syncthreads();

    // epilogue: thread owns (row = tid>>1, col half = tid&1 -> 32 cols)
    {
        int row  = tid >> 1;
        int half = tid & 1;
        int grow = row0 + row;
        if (grow < N) {
            const float* crow = Cs + row * 64 + half * 32;
            const float* asv = ag + half * 32;            // a_src slice
            const float* adv = ag + OUT_DIM + half * 32;  // a_dst slice
            float ps = 0.f, pd = 0.f;
            __half2 hv[16];
#pragma unroll
            for (int j = 0; j < 16; j++) {
                float x0 = crow[2 * j], x1 = crow[2 * j + 1];
                hv[j] = __floats2half2_rn(x0, x1);
                ps += x0 * asv[2 * j] + x1 * asv[2 * j + 1];
                pd += x0 * adv[2 * j] + x1 * adv[2 * j + 1];
            }
            uint4* dsth = (uint4*)(g_hh2 + (size_t)grow * 32 + half * 16);
            const uint4* hsrc = (const uint4*)hv;
            dsth[0] = hsrc[0]; dsth[1] = hsrc[1];
            dsth[2] = hsrc[2]; dsth[3] = hsrc[3];
            // combine the two halves of the row (adjacent lanes)
            ps += __shfl_xor_sync(0xffffffffu, ps, 1);
            pd += __shfl_xor_sync(0xffffffffu, pd, 1);
            if (half == 0) {
                g_hs[grow] = ps;
                g_hd[grow] = pd;
            }
        }
    }
}

// ---------------------------------------------------------------------------
// K2: single-pass exclusive scan of g_deg -> rowptr/cursor (decoupled lookback)
// ---------------------------------------------------------------------------
__global__ __launch_bounds__(256) void k_scan(int N) {
    __shared__ int wsum[8];
    __shared__ int s_base;
    int t = threadIdx.x, b = blockIdx.x;
    int lane = t & 31, w = t >> 5;
    int i = b * 256 + t;
    int v = (i < N) ? g_deg[i] : 0;

    int inc = v;
#pragma unroll
    for (int o = 1; o < 32; o <<= 1) {
        int u = __shfl_up_sync(0xffffffffu, inc, o);
        if (lane >= o) inc += u;
    }
    if (lane == 31) wsum[w] = inc;
    __syncthreads();
    if (w == 0) {
        int ws = (lane < 8) ? wsum[lane] : 0;
#pragma unroll
        for (int o = 1; o < 8; o <<= 1) {
            int u = __shfl_up_sync(0xffffffffu, ws, o);
            if (lane >= o) ws += u;
        }
        if (lane < 8) wsum[lane] = ws;
    }
    __syncthreads();
    int wbase = (w > 0) ? wsum[w - 1] : 0;
    int incl  = wbase + inc;
    int total = wsum[7];

    if (t == 0) {
        if (b == 0) {
            g_blockpre[0] = total;
            __threadfence();
            g_flag[0] = 2;
            s_base = 0;
        } else {
            g_blockagg[b] = total;
            __threadfence();
            g_flag[b] = 1;
            int base = 0;
            for (int j = b - 1; j >= 0; j--) {
                int f;
                while ((f = g_flag[j]) == 0) { }
                if (f == 2) { base += g_blockpre[j]; break; }
                base += g_blockagg[j];
            }
            g_blockpre[b] = base + total;
            __threadfence();
            g_flag[b] = 2;
            s_base = base;
        }
    }
    __syncthreads();

    if (i < N) {
        int p = s_base + incl - v;
        g_rowptr[i] = p;
        g_cursor[i] = p;
    }
}

// ---------------------------------------------------------------------------
// K3: scatter dst into CSR buckets (2 edges/thread); block 0 resets scan flags.
// ---------------------------------------------------------------------------
__global__ void k_scatter(const int* __restrict__ edge, int E) {
    if (blockIdx.x == 0) g_flag[threadIdx.x] = 0;
    int i0 = (blockIdx.x * blockDim.x + threadIdx.x) * 2;
#pragma unroll
    for (int u = 0; u < 2; u++) {
        int i = i0 + u;
        if (i < E) {
            int s = edge[i];
            int d = edge[E + i];
            int pos = atomicAdd(&g_cursor[s], 1);
            g_csrdst[pos] = d;
        }
    }
}

// ---------------------------------------------------------------------------
// K4: fused aggregate + softmax + ELU. One warp per node; 4 edges per inner
// step: lanes split into 4 groups of 8 (sub = lane>>3 selects the edge,
// lq = lane&7 owns dims lq*8..lq*8+7 = one uint4 = one LDG.128).
// Cross-group combine via shfl_xor(8), shfl_xor(16) at the end.
// Also resets g_deg for the next call.
// No max-shift: scores bounded, exp safe in fp32; softmax shift-invariant.
// ---------------------------------------------------------------------------
__global__ __launch_bounds__(256) void k_agg(float* __restrict__ out, int N, int E) {
    int gwarp = (blockIdx.x * blockDim.x + threadIdx.x) >> 5;
    if (gwarp >= N) return;
    int lane = threadIdx.x & 31;

    if (lane == 0) g_deg[gwarp] = 0;   // reset for next call

    int start = g_rowptr[gwarp];
    int end   = (gwarp + 1 < N) ? g_rowptr[gwarp + 1] : E;
    float hs_n = g_hs[gwarp];

    int sub = lane >> 3;                 // which edge of the quad
    int lq  = lane & 7;                  // owns dims lq*8..lq*8+7
    const uint4* hbase = (const uint4*)g_hh2 + lq;  // row stride = 8 uint4

    float a[8];
#pragma unroll
    for (int q = 0; q < 8; q++) a[q] = 0.0f;
    float spart = 0.0f;

    for (int base = start; base < end; base += 32) {
        int i = base + lane;
        bool act = (i < end);
        int dst = act ? g_csrdst[i] : 0;          // coalesced
        float hdv = act ? g_hd[dst] : 0.0f;       // parallel gather
        float sc = hs_n + hdv;
        sc = sc > 0.0f ? sc : NEG_SLOPE * sc;
        float ex = act ? __expf(sc) : 0.0f;
        spart += ex;
        int off = dst * 8;                         // uint4 row index

        int cnt = min(32, end - base);
        int steps = (cnt + 3) >> 2;
#pragma unroll 2
        for (int j = 0; j < steps; j++) {
            int e = 4 * j + sub;                   // e in 0..31; ex=0 past cnt
            float exj = __shfl_sync(0xffffffffu, ex, e);
            int offj  = __shfl_sync(0xffffffffu, off, e);
            uint4 raw = hbase[offj];
            float2 v0 = __half22float2(*(__half2*)&raw.x);
            float2 v1 = __half22float2(*(__half2*)&raw.y);
            float2 v2 = __half22float2(*(__half2*)&raw.z);
            float2 v3 = __half22float2(*(__half2*)&raw.w);
            a[0] = fmaf(exj, v0.x, a[0]); a[1] = fmaf(exj, v0.y, a[1]);
            a[2] = fmaf(exj, v1.x, a[2]); a[3] = fmaf(exj, v1.y, a[3]);
            a[4] = fmaf(exj, v2.x, a[4]); a[5] = fmaf(exj, v2.y, a[5]);
            a[6] = fmaf(exj, v3.x, a[6]); a[7] = fmaf(exj, v3.y, a[7]);
        }
    }

    // combine the 4 sub-groups (lanes lq, lq+8, lq+16, lq+24 share dims)
#pragma unroll
    for (int q = 0; q < 8; q++) {
        a[q] += __shfl_xor_sync(0xffffffffu, a[q], 8);
        a[q] += __shfl_xor_sync(0xffffffffu, a[q], 16);
    }
#pragma unroll
    for (int o = 16; o > 0; o >>= 1)
        spart += __shfl_xor_sync(0xffffffffu, spart, o);

    if (sub == 0) {   // lanes 0..7 write: node row, dims lq*8..lq*8+7
        float inv = (spart > 0.0f) ? (1.0f / spart) : 0.0f;
        float4 r0, r1;
        r0.x = a[0] * inv; r0.y = a[1] * inv; r0.z = a[2] * inv; r0.w = a[3] * inv;
        r1.x = a[4] * inv; r1.y = a[5] * inv; r1.z = a[6] * inv; r1.w = a[7] * inv;
        r0.x = r0.x > 0.f ? r0.x : expm1f(r0.x);
        r0.y = r0.y > 0.f ? r0.y : expm1f(r0.y);
        r0.z = r0.z > 0.f ? r0.z : expm1f(r0.z);
        r0.w = r0.w > 0.f ? r0.w : expm1f(r0.w);
        r1.x = r1.x > 0.f ? r1.x : expm1f(r1.x);
        r1.y = r1.y > 0.f ? r1.y : expm1f(r1.y);
        r1.z = r1.z > 0.f ? r1.z : expm1f(r1.z);
        r1.w = r1.w > 0.f ? r1.w : expm1f(r1.w);
        float4* op = (float4*)(out + (size_t)gwarp * OUT_DIM + lq * 8);
        op[0] = r0; op[1] = r1;
    }
}

// ---------------------------------------------------------------------------
extern "C" void kernel_launch(void* const* d_in, const int* in_sizes, int n_in,
                              void* d_out, int out_size) {
    const float* inp  = (const float*)d_in[0];
    const int*   edge = (const int*)d_in[1];
    const float* Wg   = (const float*)d_in[2];
    const float* ag   = (const float*)d_in[3];
    float*       out  = (float*)d_out;

    int N = in_sizes[0] / IN_DIM;
    int E = in_sizes[1] / 2;
    int nchunks = (N + 255) / 256;   // <= 256 required (N <= 65536)

    k_gemm   <<<(N + 127) / 128, 256>>>(inp, Wg, ag, edge, N, E);  // + histogram
    k_scan   <<<nchunks, 256>>>(N);
    k_scatter<<<(E / 2 + 255) / 256, 256>>>(edge, E);
    k_agg    <<<(N + 7) / 8, 256>>>(out, N, E);
}

// round 13
// speedup vs baseline: 1.1180x; 1.1180x over previous
#include <cuda_runtime.h>
#include <cuda_fp16.h>

// Problem dims: N=50000 nodes, E=800000 edges, in_dim=128, out_dim=64.
#define MAX_N   50176
#define MAX_E   803840
#define IN_DIM  128
#define OUT_DIM 64
#define NEG_SLOPE 0.2f

// Scratch (allocation-free: __device__ globals; zero-initialized at load).
__device__ __half2 g_hh2[MAX_N * (OUT_DIM / 2)];  // h [N,64] as half2
__device__ float g_hs[MAX_N];            // h @ a_src (fp32)
__device__ float g_hd[MAX_N];            // h @ a_dst (fp32)
__device__ int   g_deg[MAX_N];           // out-degree (zeroed by k_agg of prior call)
__device__ int   g_rowptr[MAX_N];        // CSR row pointers
__device__ int   g_cursor[MAX_N];        // scatter cursors
__device__ int   g_csrdst[MAX_E];        // dst ids grouped by src
// decoupled-lookback scan state + grid barrier (reset by k_gemm each call)
__device__ volatile int g_blockagg[256];
__device__ volatile int g_blockpre[256];
__device__ volatile int g_flag[256];
__device__ volatile int g_done;

// ---------------------------------------------------------------------------
// K1: h = X @ W, tiled fp32: block = 128 rows x 64 cols, thread = 8x4.
//     h stored as half2; fused hs/hd projections, src histogram, and
//     scan-state reset for this call's k_scansc.
// ---------------------------------------------------------------------------
#define AS_STRIDE 132
__global__ __launch_bounds__(256) void k_gemm(const float* __restrict__ inp,
                                              const float* __restrict__ Wg,
                                              const float* __restrict__ ag,
                                              const int* __restrict__ edge,
                                              int N, int E) {
    __shared__ float Ws[IN_DIM * OUT_DIM];      // W[k][col], 32 KB
    __shared__ float As[16 * AS_STRIDE];        // A-chunk transposed [k][row]
    __shared__ float a_s[OUT_DIM], a_d[OUT_DIM];

    int tid = threadIdx.x;
    // reset scan state for the downstream fused scan+scatter
    if (blockIdx.x == 0) {
        g_flag[tid] = 0;
        if (tid == 0) g_done = 0;
    }
    // fused histogram of edge src (g_deg pre-zeroed by prior k_agg)
    {
        int gt = blockIdx.x * 256 + tid;
        int nth = gridDim.x * 256;
        for (int i = gt; i < E; i += nth) atomicAdd(&g_deg[edge[i]], 1);
    }

    {
        const float4* src4 = (const float4*)Wg;
        float4* dst4 = (float4*)Ws;
        for (int i = tid; i < IN_DIM * OUT_DIM / 4; i += 256) dst4[i] = src4[i];
    }
    if (tid < OUT_DIM) {
        a_s[tid] = ag[tid];
        a_d[tid] = ag[OUT_DIM + tid];
    }

    int c = tid & 15;          // col group: cols c*4 .. c*4+3
    int r = tid >> 4;          // row group: rows r*8 .. r*8+7
    int row0 = blockIdx.x * 128;

    float acc[8][4];
#pragma unroll
    for (int i = 0; i < 8; i++)
#pragma unroll
        for (int j = 0; j < 4; j++) acc[i][j] = 0.0f;

    int lrow0 = tid >> 2;            // 0..63
    int lkp   = tid & 3;             // 0..3

#pragma unroll 1
    for (int kc = 0; kc < 8; kc++) {
        __syncthreads();
#pragma unroll
        for (int half = 0; half < 2; half++) {
            int row = lrow0 + half * 64;
            int grow = row0 + row;
            float4 av = (grow < N)
                ? *(const float4*)(inp + (size_t)grow * IN_DIM + kc * 16 + lkp * 4)
                : make_float4(0.f, 0.f, 0.f, 0.f);
            int kb = lkp * 4;
            As[(kb + 0) * AS_STRIDE + row] = av.x;
            As[(kb + 1) * AS_STRIDE + row] = av.y;
            As[(kb + 2) * AS_STRIDE + row] = av.z;
            As[(kb + 3) * AS_STRIDE + row] = av.w;
        }
        __syncthreads();

#pragma unroll
        for (int kk = 0; kk < 16; kk++) {
            int kg = kc * 16 + kk;
            float4 w = *(const float4*)(Ws + kg * OUT_DIM + c * 4);
            float4 aLo = *(const float4*)(As + kk * AS_STRIDE + r * 8);
            float4 aHi = *(const float4*)(As + kk * AS_STRIDE + r * 8 + 4);
            float a[8] = {aLo.x, aLo.y, aLo.z, aLo.w, aHi.x, aHi.y, aHi.z, aHi.w};
#pragma unroll
            for (int i = 0; i < 8; i++) {
                acc[i][0] = fmaf(a[i], w.x, acc[i][0]);
                acc[i][1] = fmaf(a[i], w.y, acc[i][1]);
                acc[i][2] = fmaf(a[i], w.z, acc[i][2]);
                acc[i][3] = fmaf(a[i], w.w, acc[i][3]);
            }
        }
    }

    // write h as half2 pairs
#pragma unroll
    for (int i = 0; i < 8; i++) {
        int grow = row0 + r * 8 + i;
        if (grow < N) {
            __half2* dst = g_hh2 + (size_t)grow * 32 + c * 2;
            dst[0] = __floats2half2_rn(acc[i][0], acc[i][1]);
            dst[1] = __floats2half2_rn(acc[i][2], acc[i][3]);
        }
    }

    // hs/hd projections, reduced across the 16 col-groups
    float4 asv = *(const float4*)(a_s + c * 4);
    float4 adv = *(const float4*)(a_d + c * 4);
#pragma unroll
    for (int i = 0; i < 8; i++) {
        float ps = acc[i][0] * asv.x + acc[i][1] * asv.y +
                   acc[i][2] * asv.z + acc[i][3] * asv.w;
        float pd = acc[i][0] * adv.x + acc[i][1] * adv.y +
                   acc[i][2] * adv.z + acc[i][3] * adv.w;
#pragma unroll
        for (int o = 8; o > 0; o >>= 1) {
            ps += __shfl_xor_sync(0xffffffffu, ps, o);
            pd += __shfl_xor_sync(0xffffffffu, pd, o);
        }
        int grow = row0 + r * 8 + i;
        if (c == 0 && grow < N) {
            g_hs[grow] = ps;
            g_hd[grow] = pd;
        }
    }
}

// ---------------------------------------------------------------------------
// K2 (fused): exclusive scan of g_deg -> rowptr/cursor (decoupled lookback),
// grid-wide barrier, then scatter dst into CSR buckets.
// 196 blocks, all co-resident (<= 2/SM) -> lookback and barrier are safe.
// ---------------------------------------------------------------------------
__global__ __launch_bounds__(256) void k_scansc(const int* __restrict__ edge,
                                                int N, int E) {
    __shared__ int wsum[8];
    __shared__ int s_base;
    int t = threadIdx.x, b = blockIdx.x;
    int lane = t & 31, w = t >> 5;
    int i = b * 256 + t;
    int v = (i < N) ? g_deg[i] : 0;

    // ---- phase 1: scan ----
    int inc = v;
#pragma unroll
    for (int o = 1; o < 32; o <<= 1) {
        int u = __shfl_up_sync(0xffffffffu, inc, o);
        if (lane >= o) inc += u;
    }
    if (lane == 31) wsum[w] = inc;
    __syncthreads();
    if (w == 0) {
        int ws = (lane < 8) ? wsum[lane] : 0;
#pragma unroll
        for (int o = 1; o < 8; o <<= 1) {
            int u = __shfl_up_sync(0xffffffffu, ws, o);
            if (lane >= o) ws += u;
        }
        if (lane < 8) wsum[lane] = ws;
    }
    __syncthreads();
    int wbase = (w > 0) ? wsum[w - 1] : 0;
    int incl  = wbase + inc;
    int total = wsum[7];

    if (t == 0) {
        if (b == 0) {
            g_blockpre[0] = total;
            __threadfence();
            g_flag[0] = 2;
            s_base = 0;
        } else {
            g_blockagg[b] = total;
            __threadfence();
            g_flag[b] = 1;
            int base = 0;
            for (int j = b - 1; j >= 0; j--) {
                int f;
                while ((f = g_flag[j]) == 0) { }
                if (f == 2) { base += g_blockpre[j]; break; }
                base += g_blockagg[j];
            }
            g_blockpre[b] = base + total;
            __threadfence();
            g_flag[b] = 2;
            s_base = base;
        }
    }
    __syncthreads();

    if (i < N) {
        int p = s_base + incl - v;
        g_rowptr[i] = p;
        g_cursor[i] = p;
    }

    // ---- grid-wide barrier ----
    __threadfence();
    __syncthreads();
    if (t == 0) atomicAdd((int*)&g_done, 1);
    if (t == 0) {
        while (g_done < gridDim.x) { }
    }
    __syncthreads();

    // ---- phase 2: scatter (grid-stride) ----
    int nth = gridDim.x * 256;
    for (int e = b * 256 + t; e < E; e += nth) {
        int s = edge[e];
        int d = edge[E + e];
        int pos = atomicAdd(&g_cursor[s], 1);
        g_csrdst[pos] = d;
    }
}

// ---------------------------------------------------------------------------
// K3: fused aggregate + softmax + ELU. One warp per node (R10-proven shape:
// 1 edge per lane in the parallel phase, shuffle-broadcast into the half2
// gather loop). Also resets g_deg for the next call.
// No max-shift: scores bounded, exp safe in fp32; softmax shift-invariant.
// ---------------------------------------------------------------------------
__global__ __launch_bounds__(256) void k_agg(float* __restrict__ out, int N, int E) {
    int gwarp = (blockIdx.x * blockDim.x + threadIdx.x) >> 5;
    if (gwarp >= N) return;
    int lane = threadIdx.x & 31;

    if (lane == 0) g_deg[gwarp] = 0;   // reset for next call

    int start = g_rowptr[gwarp];
    int end   = (gwarp + 1 < N) ? g_rowptr[gwarp + 1] : E;
    float hs_n = g_hs[gwarp];

    const __half2* hlane = g_hh2 + lane;   // lane's column within any row
    float a0 = 0.0f, a1 = 0.0f, spart = 0.0f;

    for (int base = start; base < end; base += 32) {
        int i = base + lane;
        bool act = (i < end);
        int dst = act ? g_csrdst[i] : 0;          // coalesced
        float hdv = act ? g_hd[dst] : 0.0f;       // parallel gather
        float sc = hs_n + hdv;
        sc = sc > 0.0f ? sc : NEG_SLOPE * sc;
        float ex = act ? __expf(sc) : 0.0f;
        spart += ex;
        int off = dst * 32;                        // pre-multiplied half2 index

        int cnt = min(32, end - base);
#pragma unroll 4
        for (int j = 0; j < cnt; j++) {
            float exj = __shfl_sync(0xffffffffu, ex, j);
            int offj  = __shfl_sync(0xffffffffu, off, j);
            float2 v = __half22float2(hlane[offj]);
            a0 = fmaf(exj, v.x, a0);
            a1 = fmaf(exj, v.y, a1);
        }
    }

#pragma unroll
    for (int o = 16; o > 0; o >>= 1)
        spart += __shfl_xor_sync(0xffffffffu, spart, o);

    float2 r;
    if (spart > 0.0f) {
        float inv = 1.0f / spart;
        r.x = a0 * inv;
        r.y = a1 * inv;
    } else {
        r.x = 0.0f; r.y = 0.0f;
    }
    r.x = r.x > 0.0f ? r.x : expm1f(r.x);
    r.y = r.y > 0.0f ? r.y : expm1f(r.y);
    ((float2*)out)[(size_t)gwarp * 32 + lane] = r;
}

// ---------------------------------------------------------------------------
extern "C" void kernel_launch(void* const* d_in, const int* in_sizes, int n_in,
                              void* d_out, int out_size) {
    const float* inp  = (const float*)d_in[0];
    const int*   edge = (const int*)d_in[1];
    const float* Wg   = (const float*)d_in[2];
    const float* ag   = (const float*)d_in[3];
    float*       out  = (float*)d_out;

    int N = in_sizes[0] / IN_DIM;
    int E = in_sizes[1] / 2;
    int nchunks = (N + 255) / 256;   // 196 blocks; must stay <= co-residency

    k_gemm  <<<(N + 127) / 128, 256>>>(inp, Wg, ag, edge, N, E);  // +hist +reset
    k_scansc<<<nchunks, 256>>>(edge, N, E);                        // scan+scatter
    k_agg   <<<(N + 7) / 8, 256>>>(out, N, E);                     // +deg reset
}

// round 14
// speedup vs baseline: 1.1263x; 1.0074x over previous
#include <cuda_runtime.h>
#include <cuda_fp16.h>

// Problem dims: N=50000 nodes, E=800000 edges, in_dim=128, out_dim=64.
#define MAX_N   50176
#define MAX_E   803840
#define IN_DIM  128
#define OUT_DIM 64
#define NEG_SLOPE 0.2f

// Scratch (allocation-free: __device__ globals; zero-initialized at load).
__device__ __half2 g_hh2[MAX_N * (OUT_DIM / 2)];  // h [N,64] as half2
__device__ float g_hs[MAX_N];            // h @ a_src (fp32)
__device__ float g_hd[MAX_N];            // h @ a_dst (fp32)
__device__ int   g_deg[MAX_N];           // out-degree (zeroed by k_agg of prior call)
__device__ int   g_rowptr[MAX_N];        // CSR row pointers
__device__ int   g_cursor[MAX_N];        // scatter cursors
__device__ int   g_csrdst[MAX_E];        // dst ids grouped by src
// decoupled-lookback scan state (flags zeroed by k_scatter of prior call)
__device__ volatile int g_blockagg[256];
__device__ volatile int g_blockpre[256];
__device__ volatile int g_flag[256];

// ---------------------------------------------------------------------------
// K1: h = X @ W, tiled fp32: block = 128 rows x 64 cols, thread = 8x4.
//     Double-buffered A staging: LDG of chunk k+1 overlaps FMAs of chunk k;
//     ONE __syncthreads per chunk. h stored as half2; fused hs/hd projections
//     (a vectors read straight from global) and src histogram.
// SMEM: Ws 32KB + 2 x As 8.25KB = 48KB exactly.
// ---------------------------------------------------------------------------
#define AS_STRIDE 132
__global__ __launch_bounds__(256) void k_gemm(const float* __restrict__ inp,
                                              const float* __restrict__ Wg,
                                              const float* __restrict__ ag,
                                              const int* __restrict__ edge,
                                              int N, int E) {
    __shared__ float Ws[IN_DIM * OUT_DIM];          // W[k][col], 32 KB
    __shared__ float As[2][16 * AS_STRIDE];         // double-buffered A chunks

    int tid = threadIdx.x;
    // fused histogram of edge src (g_deg pre-zeroed by prior k_agg)
    {
        int gt = blockIdx.x * 256 + tid;
        int nth = gridDim.x * 256;
        for (int i = gt; i < E; i += nth) atomicAdd(&g_deg[edge[i]], 1);
    }

    {
        const float4* src4 = (const float4*)Wg;
        float4* dst4 = (float4*)Ws;
        for (int i = tid; i < IN_DIM * OUT_DIM / 4; i += 256) dst4[i] = src4[i];
    }

    int c = tid & 15;          // col group: cols c*4 .. c*4+3
    int r = tid >> 4;          // row group: rows r*8 .. r*8+7
    int row0 = blockIdx.x * 128;

    float acc[8][4];
#pragma unroll
    for (int i = 0; i < 8; i++)
#pragma unroll
        for (int j = 0; j < 4; j++) acc[i][j] = 0.0f;

    int lrow0 = tid >> 2;            // 0..63
    int lkp   = tid & 3;             // 0..3
    bool okLo = (row0 + lrow0 < N);
    bool okHi = (row0 + lrow0 + 64 < N);
    const float* baseLo = inp + (size_t)(row0 + lrow0) * IN_DIM + lkp * 4;
    const float* baseHi = inp + (size_t)(row0 + lrow0 + 64) * IN_DIM + lkp * 4;
    int kb = lkp * 4;

    // prologue: stage chunk 0 into buffer 0
    float4 p0 = okLo ? *(const float4*)(baseLo) : make_float4(0.f, 0.f, 0.f, 0.f);
    float4 p1 = okHi ? *(const float4*)(baseHi) : make_float4(0.f, 0.f, 0.f, 0.f);
    {
        float* B = As[0];
        B[(kb + 0) * AS_STRIDE + lrow0] = p0.x;
        B[(kb + 1) * AS_STRIDE + lrow0] = p0.y;
        B[(kb + 2) * AS_STRIDE + lrow0] = p0.z;
        B[(kb + 3) * AS_STRIDE + lrow0] = p0.w;
        B[(kb + 0) * AS_STRIDE + lrow0 + 64] = p1.x;
        B[(kb + 1) * AS_STRIDE + lrow0 + 64] = p1.y;
        B[(kb + 2) * AS_STRIDE + lrow0 + 64] = p1.z;
        B[(kb + 3) * AS_STRIDE + lrow0 + 64] = p1.w;
    }
    __syncthreads();

#pragma unroll 1
    for (int kc = 0; kc < 8; kc++) {
        const float* cur = As[kc & 1];
        // prefetch next chunk into registers (overlaps with FMAs below)
        if (kc < 7) {
            p0 = okLo ? *(const float4*)(baseLo + (kc + 1) * 16)
                      : make_float4(0.f, 0.f, 0.f, 0.f);
            p1 = okHi ? *(const float4*)(baseHi + (kc + 1) * 16)
                      : make_float4(0.f, 0.f, 0.f, 0.f);
        }

#pragma unroll
        for (int kk = 0; kk < 16; kk++) {
            int kg = kc * 16 + kk;
            float4 w = *(const float4*)(Ws + kg * OUT_DIM + c * 4);
            float4 aLo = *(const float4*)(cur + kk * AS_STRIDE + r * 8);
            float4 aHi = *(const float4*)(cur + kk * AS_STRIDE + r * 8 + 4);
            float a[8] = {aLo.x, aLo.y, aLo.z, aLo.w, aHi.x, aHi.y, aHi.z, aHi.w};
#pragma unroll
            for (int i = 0; i < 8; i++) {
                acc[i][0] = fmaf(a[i], w.x, acc[i][0]);
                acc[i][1] = fmaf(a[i], w.y, acc[i][1]);
                acc[i][2] = fmaf(a[i], w.z, acc[i][2]);
                acc[i][3] = fmaf(a[i], w.w, acc[i][3]);
            }
        }

        if (kc < 7) {
            float* B = As[(kc + 1) & 1];
            // safe: this buffer was last READ in iteration kc-1, whose readers
            // all passed the __syncthreads at the end of that iteration.
            B[(kb + 0) * AS_STRIDE + lrow0] = p0.x;
            B[(kb + 1) * AS_STRIDE + lrow0] = p0.y;
            B[(kb + 2) * AS_STRIDE + lrow0] = p0.z;
            B[(kb + 3) * AS_STRIDE + lrow0] = p0.w;
            B[(kb + 0) * AS_STRIDE + lrow0 + 64] = p1.x;
            B[(kb + 1) * AS_STRIDE + lrow0 + 64] = p1.y;
            B[(kb + 2) * AS_STRIDE + lrow0 + 64] = p1.z;
            B[(kb + 3) * AS_STRIDE + lrow0 + 64] = p1.w;
            __syncthreads();
        }
    }

    // write h as half2 pairs
#pragma unroll
    for (int i = 0; i < 8; i++) {
        int grow = row0 + r * 8 + i;
        if (grow < N) {
            __half2* dst = g_hh2 + (size_t)grow * 32 + c * 2;
            dst[0] = __floats2half2_rn(acc[i][0], acc[i][1]);
            dst[1] = __floats2half2_rn(acc[i][2], acc[i][3]);
        }
    }

    // hs/hd projections (a vectors straight from global; tiny + cached),
    // reduced across the 16 col-groups
    float4 asv = *(const float4*)(ag + c * 4);
    float4 adv = *(const float4*)(ag + OUT_DIM + c * 4);
#pragma unroll
    for (int i = 0; i < 8; i++) {
        float ps = acc[i][0] * asv.x + acc[i][1] * asv.y +
                   acc[i][2] * asv.z + acc[i][3] * asv.w;
        float pd = acc[i][0] * adv.x + acc[i][1] * adv.y +
                   acc[i][2] * adv.z + acc[i][3] * adv.w;
#pragma unroll
        for (int o = 8; o > 0; o >>= 1) {
            ps += __shfl_xor_sync(0xffffffffu, ps, o);
            pd += __shfl_xor_sync(0xffffffffu, pd, o);
        }
        int grow = row0 + r * 8 + i;
        if (c == 0 && grow < N) {
            g_hs[grow] = ps;
            g_hd[grow] = pd;
        }
    }
}

// ---------------------------------------------------------------------------
// K2: single-pass exclusive scan of g_deg -> rowptr/cursor (decoupled lookback)
// ---------------------------------------------------------------------------
__global__ __launch_bounds__(256) void k_scan(int N) {
    __shared__ int wsum[8];
    __shared__ int s_base;
    int t = threadIdx.x, b = blockIdx.x;
    int lane = t & 31, w = t >> 5;
    int i = b * 256 + t;
    int v = (i < N) ? g_deg[i] : 0;

    int inc = v;
#pragma unroll
    for (int o = 1; o < 32; o <<= 1) {
        int u = __shfl_up_sync(0xffffffffu, inc, o);
        if (lane >= o) inc += u;
    }
    if (lane == 31) wsum[w] = inc;
    __syncthreads();
    if (w == 0) {
        int ws = (lane < 8) ? wsum[lane] : 0;
#pragma unroll
        for (int o = 1; o < 8; o <<= 1) {
            int u = __shfl_up_sync(0xffffffffu, ws, o);
            if (lane >= o) ws += u;
        }
        if (lane < 8) wsum[lane] = ws;
    }
    __syncthreads();
    int wbase = (w > 0) ? wsum[w - 1] : 0;
    int incl  = wbase + inc;
    int total = wsum[7];

    if (t == 0) {
        if (b == 0) {
            g_blockpre[0] = total;
            __threadfence();
            g_flag[0] = 2;
            s_base = 0;
        } else {
            g_blockagg[b] = total;
            __threadfence();
            g_flag[b] = 1;
            int base = 0;
            for (int j = b - 1; j >= 0; j--) {
                int f;
                while ((f = g_flag[j]) == 0) { }
                if (f == 2) { base += g_blockpre[j]; break; }
                base += g_blockagg[j];
            }
            g_blockpre[b] = base + total;
            __threadfence();
            g_flag[b] = 2;
            s_base = base;
        }
    }
    __syncthreads();

    if (i < N) {
        int p = s_base + incl - v;
        g_rowptr[i] = p;
        g_cursor[i] = p;
    }
}

// ---------------------------------------------------------------------------
// K3: scatter dst into CSR buckets (2 edges/thread); block 0 resets scan flags.
// ---------------------------------------------------------------------------
__global__ void k_scatter(const int* __restrict__ edge, int E) {
    if (blockIdx.x == 0) g_flag[threadIdx.x] = 0;
    int i0 = (blockIdx.x * blockDim.x + threadIdx.x) * 2;
#pragma unroll
    for (int u = 0; u < 2; u++) {
        int i = i0 + u;
        if (i < E) {
            int s = edge[i];
            int d = edge[E + i];
            int pos = atomicAdd(&g_cursor[s], 1);
            g_csrdst[pos] = d;
        }
    }
}

// ---------------------------------------------------------------------------
// K4: fused aggregate + softmax + ELU. One warp per node (R10-proven shape).
// Also resets g_deg for the next call.
// No max-shift: scores bounded, exp safe in fp32; softmax shift-invariant.
// ---------------------------------------------------------------------------
__global__ __launch_bounds__(256) void k_agg(float* __restrict__ out, int N, int E) {
    int gwarp = (blockIdx.x * blockDim.x + threadIdx.x) >> 5;
    if (gwarp >= N) return;
    int lane = threadIdx.x & 31;

    if (lane == 0) g_deg[gwarp] = 0;   // reset for next call

    int start = g_rowptr[gwarp];
    int end   = (gwarp + 1 < N) ? g_rowptr[gwarp + 1] : E;
    float hs_n = g_hs[gwarp];

    const __half2* hlane = g_hh2 + lane;   // lane's column within any row
    float a0 = 0.0f, a1 = 0.0f, spart = 0.0f;

    for (int base = start; base < end; base += 32) {
        int i = base + lane;
        bool act = (i < end);
        int dst = act ? g_csrdst[i] : 0;          // coalesced
        float hdv = act ? g_hd[dst] : 0.0f;       // parallel gather
        float sc = hs_n + hdv;
        sc = sc > 0.0f ? sc : NEG_SLOPE * sc;
        float ex = act ? __expf(sc) : 0.0f;
        spart += ex;
        int off = dst * 32;                        // pre-multiplied half2 index

        int cnt = min(32, end - base);
#pragma unroll 4
        for (int j = 0; j < cnt; j++) {
            float exj = __shfl_sync(0xffffffffu, ex, j);
            int offj  = __shfl_sync(0xffffffffu, off, j);
            float2 v = __half22float2(hlane[offj]);
            a0 = fmaf(exj, v.x, a0);
            a1 = fmaf(exj, v.y, a1);
        }
    }

#pragma unroll
    for (int o = 16; o > 0; o >>= 1)
        spart += __shfl_xor_sync(0xffffffffu, spart, o);

    float2 r;
    if (spart > 0.0f) {
        float inv = 1.0f / spart;
        r.x = a0 * inv;
        r.y = a1 * inv;
    } else {
        r.x = 0.0f; r.y = 0.0f;
    }
    r.x = r.x > 0.0f ? r.x : expm1f(r.x);
    r.y = r.y > 0.0f ? r.y : expm1f(r.y);
    ((float2*)out)[(size_t)gwarp * 32 + lane] = r;
}

// ---------------------------------------------------------------------------
extern "C" void kernel_launch(void* const* d_in, const int* in_sizes, int n_in,
                              void* d_out, int out_size) {
    const float* inp  = (const float*)d_in[0];
    const int*   edge = (const int*)d_in[1];
    const float* Wg   = (const float*)d_in[2];
    const float* ag   = (const float*)d_in[3];
    float*       out  = (float*)d_out;

    int N = in_sizes[0] / IN_DIM;
    int E = in_sizes[1] / 2;
    int nchunks = (N + 255) / 256;   // <= 256 required (N <= 65536)

    k_gemm   <<<(N + 127) / 128, 256>>>(inp, Wg, ag, edge, N, E);  // + histogram
    k_scan   <<<nchunks, 256>>>(N);
    k_scatter<<<(E / 2 + 255) / 256, 256>>>(edge, E);
    k_agg    <<<(N + 7) / 8, 256>>>(out, N, E);
}

// round 16
// speedup vs baseline: 1.1775x; 1.0454x over previous
#include <cuda_runtime.h>
#include <cuda_fp16.h>
#include <mma.h>

using namespace nvcuda;

// Problem dims: N=50000 nodes, E=800000 edges, in_dim=128, out_dim=64.
#define MAX_N   50176
#define MAX_E   803840
#define IN_DIM  128
#define OUT_DIM 64
#define NEG_SLOPE 0.2f

// Scratch (allocation-free: __device__ globals; zero-initialized at load).
__device__ __half2 g_hh2[MAX_N * (OUT_DIM / 2)];  // h [N,64] as half2
__device__ float g_hs[MAX_N];            // h @ a_src (fp32)
__device__ float g_hd[MAX_N];            // h @ a_dst (fp32)
__device__ int   g_deg[MAX_N];           // out-degree (zeroed by k_agg of prior call)
__device__ int   g_rowptr[MAX_N];        // CSR row pointers
__device__ int   g_cursor[MAX_N];        // scatter cursors
__device__ int   g_csrdst[MAX_E];        // dst ids grouped by src
// decoupled-lookback scan state (flags zeroed by k_scatter of prior call)
__device__ volatile int g_blockagg[256];
__device__ volatile int g_blockpre[256];
__device__ volatile int g_flag[256];

// ---------------------------------------------------------------------------
// K1: h = X @ W via wmma HMMA (fp16 in, fp32 accum), conflict-free strides.
// Block: 128 rows x 64 cols, 8 warps (warp w owns 16-row stripe, 4 n-tiles).
// K processed in two 64-wide halves; Xs restaged between halves.
// SMEM: Xs half[128][72] (18KB) + Wsh half[128][72] (18KB) = 36KB;
//       Cs float[128][64] (32KB) aliases them after the MMA phase.
// ldm = 72 halves = 144B -> fragment rows shift 4 banks/row: conflict-free.
// Fused: src histogram + hs/hd projections (from fp32 C).
// ---------------------------------------------------------------------------
#define XS_LD 72
#define WS_LD 72
__global__ __launch_bounds__(256) void k_gemm(const float* __restrict__ inp,
                                              const float* __restrict__ Wg,
                                              const float* __restrict__ ag,
                                              const int* __restrict__ edge,
                                              int N, int E) {
    __shared__ __align__(16) char smem_raw[36864];
    __half* Xs  = (__half*)smem_raw;               // [128][XS_LD]
    __half* Wsh = (__half*)(smem_raw + 18432);     // [128][WS_LD]
    float*  Cs  = (float*)smem_raw;                // [128][64] fp32 (aliases)

    int tid = threadIdx.x;
    int row0 = blockIdx.x * 128;

    // fused histogram of edge src (g_deg pre-zeroed by prior k_agg)
    {
        int gt = blockIdx.x * 256 + tid;
        int nth = gridDim.x * 256;
        for (int i = gt; i < E; i += nth) atomicAdd(&g_deg[edge[i]], 1);
    }

    // stage W [128][64] fp32 -> fp16 once (rows = k, ldm = WS_LD)
    {
        const float4* W4 = (const float4*)Wg;
#pragma unroll
        for (int u = 0; u < 8; u++) {
            int i = tid + u * 256;                 // 2048 float4 total
            float4 f = W4[i];
            int krow = i >> 4;
            int col  = (i & 15) * 4;
            __half2* p = (__half2*)(Wsh + krow * WS_LD + col);
            p[0] = __floats2half2_rn(f.x, f.y);
            p[1] = __floats2half2_rn(f.z, f.w);
        }
    }

    int w = tid >> 5;
    wmma::fragment<wmma::accumulator, 16, 16, 16, float> c_frag[4];
#pragma unroll
    for (int n = 0; n < 4; n++) wmma::fill_fragment(c_frag[n], 0.0f);

    // X staging: thread handles row = tid>>1; within the current 64-wide
    // k-half, the 16 float4s are split between the two threads of the row:
    // c4 = xq0 + q in 0..15 (offset *within the half*).
    int xrow  = tid >> 1;
    int xq0   = (tid & 1) * 8;
    bool rok  = (row0 + xrow < N);
    const float4* Xrow4 = (const float4*)(inp + (size_t)(row0 + xrow) * IN_DIM);

#pragma unroll
    for (int kh = 0; kh < 2; kh++) {
        if (kh) __syncthreads();   // ensure prior half's readers are done
        {
#pragma unroll
            for (int q = 0; q < 8; q++) {
                int c4 = xq0 + q;                  // float4 index within the half
                float4 f = rok ? Xrow4[kh * 16 + c4]
                               : make_float4(0.f, 0.f, 0.f, 0.f);
                __half2* p = (__half2*)(Xs + xrow * XS_LD + c4 * 4);
                p[0] = __floats2half2_rn(f.x, f.y);
                p[1] = __floats2half2_rn(f.z, f.w);
            }
        }
        __syncthreads();

#pragma unroll
        for (int k = 0; k < 4; k++) {
            wmma::fragment<wmma::matrix_a, 16, 16, 16, __half, wmma::row_major> a_frag;
            wmma::load_matrix_sync(a_frag, Xs + w * 16 * XS_LD + k * 16, XS_LD);
#pragma unroll
            for (int n = 0; n < 4; n++) {
                wmma::fragment<wmma::matrix_b, 16, 16, 16, __half, wmma::row_major> b_frag;
                wmma::load_matrix_sync(b_frag,
                    Wsh + (kh * 64 + k * 16) * WS_LD + n * 16, WS_LD);
                wmma::mma_sync(c_frag[n], a_frag, b_frag, c_frag[n]);
            }
        }
    }
    __syncthreads();   // MMA done; smem reusable as Cs

#pragma unroll
    for (int n = 0; n < 4; n++)
        wmma::store_matrix_sync(Cs + w * 16 * 64 + n * 16, c_frag[n], 64,
                                wmma::mem_row_major);
    __syncthreads();

    // epilogue: thread owns (row = tid>>1, half-row = tid&1 -> 32 cols)
    {
        int row  = tid >> 1;
        int half = tid & 1;
        int grow = row0 + row;
        if (grow < N) {
            const float* crow = Cs + row * 64 + half * 32;
            const float* asv = ag + half * 32;            // a_src slice
            const float* adv = ag + OUT_DIM + half * 32;  // a_dst slice
            float ps = 0.f, pd = 0.f;
            __half2 hv[16];
#pragma unroll
            for (int j = 0; j < 16; j++) {
                float x0 = crow[2 * j], x1 = crow[2 * j + 1];
                hv[j] = __floats2half2_rn(x0, x1);
                ps += x0 * asv[2 * j] + x1 * asv[2 * j + 1];
                pd += x0 * adv[2 * j] + x1 * adv[2 * j + 1];
            }
            uint4* dsth = (uint4*)(g_hh2 + (size_t)grow * 32 + half * 16);
            const uint4* hsrc = (const uint4*)hv;
            dsth[0] = hsrc[0]; dsth[1] = hsrc[1];
            dsth[2] = hsrc[2]; dsth[3] = hsrc[3];
            ps += __shfl_xor_sync(0xffffffffu, ps, 1);
            pd += __shfl_xor_sync(0xffffffffu, pd, 1);
            if (half == 0) {
                g_hs[grow] = ps;
                g_hd[grow] = pd;
            }
        }
    }
}

// ---------------------------------------------------------------------------
// K2: single-pass exclusive scan of g_deg -> rowptr/cursor (decoupled lookback)
// ---------------------------------------------------------------------------
__global__ __launch_bounds__(256) void k_scan(int N) {
    __shared__ int wsum[8];
    __shared__ int s_base;
    int t = threadIdx.x, b = blockIdx.x;
    int lane = t & 31, w = t >> 5;
    int i = b * 256 + t;
    int v = (i < N) ? g_deg[i] : 0;

    int inc = v;
#pragma unroll
    for (int o = 1; o < 32; o <<= 1) {
        int u = __shfl_up_sync(0xffffffffu, inc, o);
        if (lane >= o) inc += u;
    }
    if (lane == 31) wsum[w] = inc;
    __syncthreads();
    if (w == 0) {
        int ws = (lane < 8) ? wsum[lane] : 0;
#pragma unroll
        for (int o = 1; o < 8; o <<= 1) {
            int u = __shfl_up_sync(0xffffffffu, ws, o);
            if (lane >= o) ws += u;
        }
        if (lane < 8) wsum[lane] = ws;
    }
    __syncthreads();
    int wbase = (w > 0) ? wsum[w - 1] : 0;
    int incl  = wbase + inc;
    int total = wsum[7];

    if (t == 0) {
        if (b == 0) {
            g_blockpre[0] = total;
            __threadfence();
            g_flag[0] = 2;
            s_base = 0;
        } else {
            g_blockagg[b] = total;
            __threadfence();
            g_flag[b] = 1;
            int base = 0;
            for (int j = b - 1; j >= 0; j--) {
                int f;
                while ((f = g_flag[j]) == 0) { }
                if (f == 2) { base += g_blockpre[j]; break; }
                base += g_blockagg[j];
            }
            g_blockpre[b] = base + total;
            __threadfence();
            g_flag[b] = 2;
            s_base = base;
        }
    }
    __syncthreads();

    if (i < N) {
        int p = s_base + incl - v;
        g_rowptr[i] = p;
        g_cursor[i] = p;
    }
}

// ---------------------------------------------------------------------------
// K3: scatter dst into CSR buckets (2 edges/thread); block 0 resets scan flags.
// ---------------------------------------------------------------------------
__global__ void k_scatter(const int* __restrict__ edge, int E) {
    if (blockIdx.x == 0) g_flag[threadIdx.x] = 0;
    int i0 = (blockIdx.x * blockDim.x + threadIdx.x) * 2;
#pragma unroll
    for (int u = 0; u < 2; u++) {
        int i = i0 + u;
        if (i < E) {
            int s = edge[i];
            int d = edge[E + i];
            int pos = atomicAdd(&g_cursor[s], 1);
            g_csrdst[pos] = d;
        }
    }
}

// ---------------------------------------------------------------------------
// K4: fused aggregate + softmax + ELU. One warp per node (R10-proven shape).
// Also resets g_deg for the next call.
// No max-shift: scores bounded, exp safe in fp32; softmax shift-invariant.
// ---------------------------------------------------------------------------
__global__ __launch_bounds__(256) void k_agg(float* __restrict__ out, int N, int E) {
    int gwarp = (blockIdx.x * blockDim.x + threadIdx.x) >> 5;
    if (gwarp >= N) return;
    int lane = threadIdx.x & 31;

    if (lane == 0) g_deg[gwarp] = 0;   // reset for next call

    int start = g_rowptr[gwarp];
    int end   = (gwarp + 1 < N) ? g_rowptr[gwarp + 1] : E;
    float hs_n = g_hs[gwarp];

    const __half2* hlane = g_hh2 + lane;   // lane's column within any row
    float a0 = 0.0f, a1 = 0.0f, spart = 0.0f;

    for (int base = start; base < end; base += 32) {
        int i = base + lane;
        bool act = (i < end);
        int dst = act ? g_csrdst[i] : 0;          // coalesced
        float hdv = act ? g_hd[dst] : 0.0f;       // parallel gather
        float sc = hs_n + hdv;
        sc = sc > 0.0f ? sc : NEG_SLOPE * sc;
        float ex = act ? __expf(sc) : 0.0f;
        spart += ex;
        int off = dst * 32;                        // pre-multiplied half2 index

        int cnt = min(32, end - base);
#pragma unroll 4
        for (int j = 0; j < cnt; j++) {
            float exj = __shfl_sync(0xffffffffu, ex, j);
            int offj  = __shfl_sync(0xffffffffu, off, j);
            float2 v = __half22float2(hlane[offj]);
            a0 = fmaf(exj, v.x, a0);
            a1 = fmaf(exj, v.y, a1);
        }
    }

#pragma unroll
    for (int o = 16; o > 0; o >>= 1)
        spart += __shfl_xor_sync(0xffffffffu, spart, o);

    float2 r;
    if (spart > 0.0f) {
        float inv = 1.0f / spart;
        r.x = a0 * inv;
        r.y = a1 * inv;
    } else {
        r.x = 0.0f; r.y = 0.0f;
    }
    r.x = r.x > 0.0f ? r.x : expm1f(r.x);
    r.y = r.y > 0.0f ? r.y : expm1f(r.y);
    ((float2*)out)[(size_t)gwarp * 32 + lane] = r;
}

// ---------------------------------------------------------------------------
extern "C" void kernel_launch(void* const* d_in, const int* in_sizes, int n_in,
                              void* d_out, int out_size) {
    const float* inp  = (const float*)d_in[0];
    const int*   edge = (const int*)d_in[1];
    const float* Wg   = (const float*)d_in[2];
    const float* ag   = (const float*)d_in[3];
    float*       out  = (float*)d_out;

    int N = in_sizes[0] / IN_DIM;
    int E = in_sizes[1] / 2;
    int nchunks = (N + 255) / 256;   // <= 256 required (N <= 65536)

    k_gemm   <<<(N + 127) / 128, 256>>>(inp, Wg, ag, edge, N, E);  // + histogram
    k_scan   <<<nchunks, 256>>>(N);
    k_scatter<<<(E / 2 + 255) / 256, 256>>>(edge, E);
    k_agg    <<<(N + 7) / 8, 256>>>(out, N, E);
}

// round 17
// speedup vs baseline: 1.2447x; 1.0571x over previous
#include <cuda_runtime.h>
#include <cuda_fp16.h>
#include <mma.h>

using namespace nvcuda;

// Problem dims: N=50000 nodes, E=800000 edges, in_dim=128, out_dim=64.
#define MAX_N   50176
#define MAX_E   803840
#define IN_DIM  128
#define OUT_DIM 64
#define NEG_SLOPE 0.2f

// Scratch (allocation-free: __device__ globals; zero-initialized at load).
__device__ __half2 g_hh2[MAX_N * (OUT_DIM / 2)];  // h [N,64] as half2
__device__ float g_hs[MAX_N];            // h @ a_src (fp32)
__device__ float g_hd[MAX_N];            // h @ a_dst (fp32)
__device__ int   g_deg[MAX_N];           // out-degree (zeroed by k_agg of prior call)
__device__ int   g_rowptr[MAX_N];        // CSR row pointers
__device__ int   g_cursor[MAX_N];        // scatter cursors
__device__ int   g_csrdst[MAX_E];        // dst ids grouped by src
// decoupled-lookback scan state (flags zeroed by k_scatter of prior call)
__device__ volatile int g_blockagg[256];
__device__ volatile int g_blockpre[256];
__device__ volatile int g_flag[256];

// ---------------------------------------------------------------------------
// K1: h = X @ W via wmma HMMA. Block: 64 rows x 64 cols (782 blocks -> ~6
// resident/SM, hides staging latency). 8 warps: warp w owns rows (w&3)*16,
// cols (w>>2)*32 (2 n-tiles), K=128 fully resident in Xs.
// SMEM: Xs half[64][136] 17.4KB + Wsh half[128][72] 18KB = 35.4KB;
//       Cs float[64][64] 16KB aliases Xs after MMA.
// Row strides 136/72 halves -> 4-bank shift per row: conflict-free fragments.
// Fused: src histogram + hs/hd projections.
// ---------------------------------------------------------------------------
#define XS_LD 136
#define WS_LD 72
__global__ __launch_bounds__(256) void k_gemm(const float* __restrict__ inp,
                                              const float* __restrict__ Wg,
                                              const float* __restrict__ ag,
                                              const int* __restrict__ edge,
                                              int N, int E) {
    __shared__ __align__(16) char smem_raw[17408 + 18432];
    __half* Xs  = (__half*)smem_raw;                 // [64][XS_LD]
    __half* Wsh = (__half*)(smem_raw + 17408);       // [128][WS_LD]
    float*  Cs  = (float*)smem_raw;                  // [64][64] fp32 (aliases Xs)

    int tid = threadIdx.x;
    int row0 = blockIdx.x * 64;

    // fused histogram of edge src (g_deg pre-zeroed by prior k_agg)
    {
        int gt = blockIdx.x * 256 + tid;
        int nth = gridDim.x * 256;
        for (int i = gt; i < E; i += nth) atomicAdd(&g_deg[edge[i]], 1);
    }

    // stage W [128][64] fp32 -> fp16 (rows = k, ldm = WS_LD)
    {
        const float4* W4 = (const float4*)Wg;
#pragma unroll
        for (int u = 0; u < 8; u++) {
            int i = tid + u * 256;                   // 2048 float4 total
            float4 f = W4[i];
            int krow = i >> 4;
            int col  = (i & 15) * 4;
            __half2* p = (__half2*)(Wsh + krow * WS_LD + col);
            p[0] = __floats2half2_rn(f.x, f.y);
            p[1] = __floats2half2_rn(f.z, f.w);
        }
    }

    // stage X block [64][128] fp32 -> fp16 (full K), ldm = XS_LD
    {
        int xrow = tid >> 2;                         // 0..63
        int xc   = tid & 3;                          // float4 phase
        bool rok = (row0 + xrow < N);
        const float4* Xrow4 = (const float4*)(inp + (size_t)(row0 + xrow) * IN_DIM);
#pragma unroll
        for (int q = 0; q < 8; q++) {
            int c4 = xc + q * 4;                     // 0..31
            float4 f = rok ? Xrow4[c4] : make_float4(0.f, 0.f, 0.f, 0.f);
            __half2* p = (__half2*)(Xs + xrow * XS_LD + c4 * 4);
            p[0] = __floats2half2_rn(f.x, f.y);
            p[1] = __floats2half2_rn(f.z, f.w);
        }
    }
    __syncthreads();

    int w  = tid >> 5;
    int rw = (w & 3) * 16;
    int cw = (w >> 2) * 32;
    wmma::fragment<wmma::accumulator, 16, 16, 16, float> c_frag[2];
#pragma unroll
    for (int n = 0; n < 2; n++) wmma::fill_fragment(c_frag[n], 0.0f);

#pragma unroll
    for (int k = 0; k < 8; k++) {
        wmma::fragment<wmma::matrix_a, 16, 16, 16, __half, wmma::row_major> a_frag;
        wmma::load_matrix_sync(a_frag, Xs + rw * XS_LD + k * 16, XS_LD);
#pragma unroll
        for (int n = 0; n < 2; n++) {
            wmma::fragment<wmma::matrix_b, 16, 16, 16, __half, wmma::row_major> b_frag;
            wmma::load_matrix_sync(b_frag, Wsh + (k * 16) * WS_LD + cw + n * 16, WS_LD);
            wmma::mma_sync(c_frag[n], a_frag, b_frag, c_frag[n]);
        }
    }
    __syncthreads();   // all MMA reads done; Xs reusable as Cs

#pragma unroll
    for (int n = 0; n < 2; n++)
        wmma::store_matrix_sync(Cs + rw * 64 + cw + n * 16, c_frag[n], 64,
                                wmma::mem_row_major);
    __syncthreads();

    // epilogue: thread owns (row = tid>>2, quarter = tid&3 -> 16 cols)
    {
        int row = tid >> 2;
        int qt  = tid & 3;
        int grow = row0 + row;
        if (grow < N) {
            const float* crow = Cs + row * 64 + qt * 16;
            const float* asv = ag + qt * 16;
            const float* adv = ag + OUT_DIM + qt * 16;
            float ps = 0.f, pd = 0.f;
            __half2 hv[8];
#pragma unroll
            for (int j = 0; j < 8; j++) {
                float x0 = crow[2 * j], x1 = crow[2 * j + 1];
                hv[j] = __floats2half2_rn(x0, x1);
                ps += x0 * asv[2 * j] + x1 * asv[2 * j + 1];
                pd += x0 * adv[2 * j] + x1 * adv[2 * j + 1];
            }
            uint4* dsth = (uint4*)(g_hh2 + (size_t)grow * 32 + qt * 8);
            const uint4* hsrc = (const uint4*)hv;
            dsth[0] = hsrc[0]; dsth[1] = hsrc[1];
            // reduce ps/pd across the 4 lanes of this row
            ps += __shfl_xor_sync(0xffffffffu, ps, 1);
            pd += __shfl_xor_sync(0xffffffffu, pd, 1);
            ps += __shfl_xor_sync(0xffffffffu, ps, 2);
            pd += __shfl_xor_sync(0xffffffffu, pd, 2);
            if (qt == 0) {
                g_hs[grow] = ps;
                g_hd[grow] = pd;
            }
        }
    }
}

// ---------------------------------------------------------------------------
// K2: single-pass exclusive scan of g_deg -> rowptr/cursor (decoupled lookback)
// ---------------------------------------------------------------------------
__global__ __launch_bounds__(256) void k_scan(int N) {
    __shared__ int wsum[8];
    __shared__ int s_base;
    int t = threadIdx.x, b = blockIdx.x;
    int lane = t & 31, w = t >> 5;
    int i = b * 256 + t;
    int v = (i < N) ? g_deg[i] : 0;

    int inc = v;
#pragma unroll
    for (int o = 1; o < 32; o <<= 1) {
        int u = __shfl_up_sync(0xffffffffu, inc, o);
        if (lane >= o) inc += u;
    }
    if (lane == 31) wsum[w] = inc;
    __syncthreads();
    if (w == 0) {
        int ws = (lane < 8) ? wsum[lane] : 0;
#pragma unroll
        for (int o = 1; o < 8; o <<= 1) {
            int u = __shfl_up_sync(0xffffffffu, ws, o);
            if (lane >= o) ws += u;
        }
        if (lane < 8) wsum[lane] = ws;
    }
    __syncthreads();
    int wbase = (w > 0) ? wsum[w - 1] : 0;
    int incl  = wbase + inc;
    int total = wsum[7];

    if (t == 0) {
        if (b == 0) {
            g_blockpre[0] = total;
            __threadfence();
            g_flag[0] = 2;
            s_base = 0;
        } else {
            g_blockagg[b] = total;
            __threadfence();
            g_flag[b] = 1;
            int base = 0;
            for (int j = b - 1; j >= 0; j--) {
                int f;
                while ((f = g_flag[j]) == 0) { }
                if (f == 2) { base += g_blockpre[j]; break; }
                base += g_blockagg[j];
            }
            g_blockpre[b] = base + total;
            __threadfence();
            g_flag[b] = 2;
            s_base = base;
        }
    }
    __syncthreads();

    if (i < N) {
        int p = s_base + incl - v;
        g_rowptr[i] = p;
        g_cursor[i] = p;
    }
}

// ---------------------------------------------------------------------------
// K3: scatter dst into CSR buckets (4 edges/thread, int4 index loads);
// block 0 resets scan flags.
// ---------------------------------------------------------------------------
__global__ void k_scatter(const int* __restrict__ edge, int E) {
    if (blockIdx.x == 0) g_flag[threadIdx.x] = 0;
    int i0 = (blockIdx.x * blockDim.x + threadIdx.x) * 4;
    if (i0 + 3 < E) {
        int4 s4 = *(const int4*)(edge + i0);
        int4 d4 = *(const int4*)(edge + E + i0);
        g_csrdst[atomicAdd(&g_cursor[s4.x], 1)] = d4.x;
        g_csrdst[atomicAdd(&g_cursor[s4.y], 1)] = d4.y;
        g_csrdst[atomicAdd(&g_cursor[s4.z], 1)] = d4.z;
        g_csrdst[atomicAdd(&g_cursor[s4.w], 1)] = d4.w;
    } else {
        for (int i = i0; i < E; i++) {
            int s = edge[i];
            int d = edge[E + i];
            g_csrdst[atomicAdd(&g_cursor[s], 1)] = d;
        }
    }
}

// ---------------------------------------------------------------------------
// K4: fused aggregate + softmax + ELU. One warp per node (R10-proven shape).
// Also resets g_deg for the next call.
// No max-shift: scores bounded, exp safe in fp32; softmax shift-invariant.
// ---------------------------------------------------------------------------
__global__ __launch_bounds__(256) void k_agg(float* __restrict__ out, int N, int E) {
    int gwarp = (blockIdx.x * blockDim.x + threadIdx.x) >> 5;
    if (gwarp >= N) return;
    int lane = threadIdx.x & 31;

    if (lane == 0) g_deg[gwarp] = 0;   // reset for next call

    int start = g_rowptr[gwarp];
    int end   = (gwarp + 1 < N) ? g_rowptr[gwarp + 1] : E;
    float hs_n = g_hs[gwarp];

    const __half2* hlane = g_hh2 + lane;   // lane's column within any row
    float a0 = 0.0f, a1 = 0.0f, spart = 0.0f;

    for (int base = start; base < end; base += 32) {
        int i = base + lane;
        bool act = (i < end);
        int dst = act ? g_csrdst[i] : 0;          // coalesced
        float hdv = act ? g_hd[dst] : 0.0f;       // parallel gather
        float sc = hs_n + hdv;
        sc = sc > 0.0f ? sc : NEG_SLOPE * sc;
        float ex = act ? __expf(sc) : 0.0f;
        spart += ex;
        int off = dst * 32;                        // pre-multiplied half2 index

        int cnt = min(32, end - base);
#pragma unroll 4
        for (int j = 0; j < cnt; j++) {
            float exj = __shfl_sync(0xffffffffu, ex, j);
            int offj  = __shfl_sync(0xffffffffu, off, j);
            float2 v = __half22float2(hlane[offj]);
            a0 = fmaf(exj, v.x, a0);
            a1 = fmaf(exj, v.y, a1);
        }
    }

#pragma unroll
    for (int o = 16; o > 0; o >>= 1)
        spart += __shfl_xor_sync(0xffffffffu, spart, o);

    float2 r;
    if (spart > 0.0f) {
        float inv = 1.0f / spart;
        r.x = a0 * inv;
        r.y = a1 * inv;
    } else {
        r.x = 0.0f; r.y = 0.0f;
    }
    r.x = r.x > 0.0f ? r.x : expm1f(r.x);
    r.y = r.y > 0.0f ? r.y : expm1f(r.y);
    ((float2*)out)[(size_t)gwarp * 32 + lane] = r;
}

// ---------------------------------------------------------------------------
extern "C" void kernel_launch(void* const* d_in, const int* in_sizes, int n_in,
                              void* d_out, int out_size) {
    const float* inp  = (const float*)d_in[0];
    const int*   edge = (const int*)d_in[1];
    const float* Wg   = (const float*)d_in[2];
    const float* ag   = (const float*)d_in[3];
    float*       out  = (float*)d_out;

    int N = in_sizes[0] / IN_DIM;
    int E = in_sizes[1] / 2;
    int nchunks = (N + 255) / 256;   // <= 256 required (N <= 65536)

    k_gemm   <<<(N + 63) / 64, 256>>>(inp, Wg, ag, edge, N, E);   // + histogram
    k_scan   <<<nchunks, 256>>>(N);
    k_scatter<<<(E / 4 + 255) / 256, 256>>>(edge, E);
    k_agg    <<<(N + 7) / 8, 256>>>(out, N, E);
}